// round 7
// baseline (speedup 1.0000x reference)
#include <cuda_runtime.h>
#include <cstdint>

// CTC loss forward: T=2048, N=64, C=256, S=256, E=2S+1=513.
// One CTA per batch element. Alpha recurrence in LOG2 domain (lse3 via
// 3x EX2 + 1x LG2 per state-step) -- matches reference semantics exactly,
// no dynamic-range hazard (R6 failure: prob-domain denormal corruption).
// x rows prefetched via cp.async ring driven by WARP 16; one __syncthreads
// per timestep publishes new alpha + next row.

#define Tdim 2048
#define Nb   64
#define Cdim 256
#define Sdim 256
#define Edim (2 * Sdim + 1)   // 513
#define THREADS 544           // 17 warps; threads 0..512 own alpha states
#define DEPTH 6               // cp.async ring depth (rows of x)

#define LOG2E 1.4426950408889634f
#define LN2   0.6931471805599453f
#define NEG2  (-1.0e30f)      // absorbing "log zero" (reference uses -1e30)

__device__ float g_block_loss[Nb];

__device__ __forceinline__ void cp_async16(uint32_t saddr, const void* gaddr) {
    asm volatile("cp.async.cg.shared.global [%0], [%1], 16;\n"
                 :: "r"(saddr), "l"(gaddr));
}
__device__ __forceinline__ void cp_commit() {
    asm volatile("cp.async.commit_group;\n");
}
template <int N>
__device__ __forceinline__ void cp_wait() {
    asm volatile("cp.async.wait_group %0;\n" :: "n"(N));
}

__global__ __launch_bounds__(THREADS, 1)
void ctc_alpha_kernel(const float* __restrict__ x,
                      const int*   __restrict__ y,
                      const int*   __restrict__ ilen,
                      const int*   __restrict__ tlen)
{
    // xrow first + 16B-aligned: cp.async 16B needs 16B-aligned shared dst.
    __shared__ __align__(16) float xrow[DEPTH][Cdim];   // ring of log-prob rows
    __shared__ float bufA[2 + Edim];   // pads [0..1] = NEG2 -> branch-free s-1/s-2
    __shared__ float bufB[2 + Edim];

    const int n   = blockIdx.x;
    const int tid = threadIdx.x;
    const int L   = tlen[n];
    const int En  = 2 * L + 1;
    const int len = ilen[n];

    // Per-thread static state: extended label + skip flag.
    const int s = tid;
    const bool active = (s < En);
    int  lab = 0;
    bool sk  = false;
    if (active && (s & 1)) {
        lab = y[n * Sdim + (s >> 1)];
        if (s >= 3) sk = (lab != y[n * Sdim + ((s - 2) >> 1)]);
    }

    // Init both alpha buffers (incl. pads) to log-zero.
    for (int i = tid; i < 2 + Edim; i += THREADS) { bufA[i] = NEG2; bufB[i] = NEG2; }

    const float*  xbase   = x + (size_t)n * Cdim;      // + t*Nb*Cdim for row t
    const size_t  rstride = (size_t)Nb * Cdim;         // floats per timestep
    const uint32_t sxrow  = (uint32_t)__cvta_generic_to_shared(&xrow[0][0]);

    // Prefetch role: warp 16 (tids 512..543). 32 threads x 2 x 16B = 1024B row.
    const bool pf   = (tid >= 512);
    const int  lane = tid - 512;

    // ---- Prologue: prefetch rows 0..DEPTH-2, publish row 0 ----
    if (pf) {
        #pragma unroll
        for (int t0 = 0; t0 < DEPTH - 1; ++t0) {
            const float* g = xbase + (size_t)t0 * rstride + lane * 8;
            uint32_t     a = sxrow + (uint32_t)(t0 * Cdim + lane * 8) * 4;
            cp_async16(a,      g);
            cp_async16(a + 16, g + 4);
            cp_commit();
        }
        cp_wait<DEPTH - 2>();   // row 0 complete
    }
    __syncthreads();

    // alpha_0 init (log2 domain): A[0] = x[0,n,blank]*log2e; A[1] = x[0,n,y0]*log2e
    if (tid == 0) bufA[2] = xrow[0][0]   * LOG2E;
    if (tid == 1) bufA[3] = xrow[0][lab] * LOG2E;

    if (pf) {
        const float* g = xbase + (size_t)(DEPTH - 1) * rstride + lane * 8;
        uint32_t     a = sxrow + (uint32_t)((DEPTH - 1) * Cdim + lane * 8) * 4;
        cp_async16(a,      g);
        cp_async16(a + 16, g + 4);
        cp_commit();
        cp_wait<DEPTH - 2>();   // row 1 complete
    }
    __syncthreads();

    float* Acur  = bufA;
    float* Bnext = bufB;

    float a_own = active ? Acur[2 + s] : NEG2;   // own previous alpha (log2)

    int slot_rd = 1;   // slot holding row t (t starts at 1)
    int slot_wr = 0;   // slot to overwrite: (t-1) % DEPTH

    for (int t = 1; t < len; ++t) {
        // -- alpha update (row t published by previous barrier) --
        if (active) {
            const float xv2 = xrow[slot_rd][lab] * LOG2E;
            const float a2  = Acur[1 + s];
            const float a3  = sk ? Acur[s] : NEG2;
            // lse3 in base-2
            const float m   = fmaxf(fmaxf(a_own, a2), a3);
            const float sum = exp2f(a_own - m) + exp2f(a2 - m) + exp2f(a3 - m);
            const float v   = m + log2f(sum) + xv2;
            Bnext[2 + s] = v;
            a_own = v;
        }

        // -- prefetch row t+DEPTH-1 into the slot consumed last iteration --
        if (pf) {
            int tr = t + DEPTH - 1;
            if (tr > Tdim - 1) tr = Tdim - 1;   // clamped rows never consumed
            const float* g = xbase + (size_t)tr * rstride + lane * 8;
            uint32_t     a = sxrow + (uint32_t)(slot_wr * Cdim + lane * 8) * 4;
            cp_async16(a,      g);
            cp_async16(a + 16, g + 4);
            cp_commit();
            cp_wait<DEPTH - 2>();               // row t+1 complete
        }

        __syncthreads();   // publishes Bnext and row t+1

        // advance ring slots without modulo
        slot_rd = (slot_rd + 1 == DEPTH) ? 0 : slot_rd + 1;
        slot_wr = (slot_wr + 1 == DEPTH) ? 0 : slot_wr + 1;

        // swap alpha buffers
        float* tmp = Acur; Acur = Bnext; Bnext = tmp;
    }

    if (tid == 0) {
        // log-likelihood: logaddexp of the two final states (base-2 -> nat)
        const float l1 = Acur[2 + (2 * L - 1)];
        const float l2 = Acur[2 + 2 * L];
        const float m  = fmaxf(l1, l2);
        const float ll2 = m + log2f(exp2f(l1 - m) + exp2f(l2 - m));
        g_block_loss[n] = -(ll2 * LN2) / (float)L;
    }
}

__global__ void ctc_reduce_kernel(float* __restrict__ out)
{
    const int tid = threadIdx.x;   // 64 threads
    float v = g_block_loss[tid];
    #pragma unroll
    for (int off = 16; off > 0; off >>= 1)
        v += __shfl_xor_sync(0xffffffffu, v, off);
    __shared__ float w[2];
    if ((tid & 31) == 0) w[tid >> 5] = v;
    __syncthreads();
    if (tid == 0) out[0] = (w[0] + w[1]) * (1.0f / (float)Nb);
}

extern "C" void kernel_launch(void* const* d_in, const int* in_sizes, int n_in,
                              void* d_out, int out_size)
{
    (void)in_sizes; (void)n_in; (void)out_size;
    const float* x  = (const float*)d_in[0];
    const int*   y  = (const int*)d_in[1];
    const int*   il = (const int*)d_in[2];
    const int*   tl = (const int*)d_in[3];

    ctc_alpha_kernel<<<Nb, THREADS>>>(x, y, il, tl);
    ctc_reduce_kernel<<<1, 64>>>((float*)d_out);
}

// round 9
// speedup vs baseline: 1.2354x; 1.2354x over previous
#include <cuda_runtime.h>
#include <cstdint>

// CTC loss forward: T=2048, N=64, C=256, S=256, E=2S+1=513.
// One CTA per batch element. Alpha recurrence in EXTENDED-RANGE LINEAR domain:
// each state = (mantissa in [1,2), int32 exponent). The lse3 becomes a plain
// 3-term sum with power-of-2 alignment done via exponent-field bit ops; the
// only MUFU op per state-step is one exp2f for p_t (off the dependency chain).
// R7 log-domain (4 MUFU/step) ran 399.9us; this removes 3 MUFU and shortens
// the serial chain. Accuracy: fp32-rounding-exact; per-state exponent kills
// the R6 denormal hazard (v = sum*p is always normal-or-zero, audited R8).
// x rows prefetched via cp.async ring driven by WARP 16; one __syncthreads
// per timestep publishes new alpha + next row.

#define Tdim 2048
#define Nb   64
#define Cdim 256
#define Sdim 256
#define Edim (2 * Sdim + 1)   // 513
#define THREADS 544           // 17 warps; threads 0..512 own alpha states
#define DEPTH 6               // cp.async ring depth (rows of x)

#define LOG2E 1.4426950408889634f
#define LN2   0.6931471805599453f
#define NEGL  (-1.0e30f)      // log-zero for final readout
#define BIGE  (-(1 << 28))    // exponent of the zero state

__device__ float g_block_loss[Nb];

__device__ __forceinline__ void cp_async16(uint32_t saddr, const void* gaddr) {
    asm volatile("cp.async.cg.shared.global [%0], [%1], 16;\n"
                 :: "r"(saddr), "l"(gaddr));
}
__device__ __forceinline__ void cp_commit() {
    asm volatile("cp.async.commit_group;\n");
}
template <int N>
__device__ __forceinline__ void cp_wait() {
    asm volatile("cp.async.wait_group %0;\n" :: "n"(N));
}

// 2^d as a float for d <= 0, exact; d <= -127 -> 0.0f (matches the reference's
// own exp() underflow window in its lse3).
__device__ __forceinline__ float pow2i(int d) {
    d = max(d, -127);
    return __int_as_float((d + 127) << 23);
}

__global__ __launch_bounds__(THREADS, 1)
void ctc_alpha_kernel(const float* __restrict__ x,
                      const int*   __restrict__ y,
                      const int*   __restrict__ ilen,
                      const int*   __restrict__ tlen)
{
    // xrow first + 16B-aligned: cp.async 16B needs 16B-aligned shared dst.
    __shared__ __align__(16) float xrow[DEPTH][Cdim];   // ring of log-prob rows
    // alpha as (mant, exponent-bits) pairs; pads [0..1] = zero state.
    __shared__ __align__(16) float2 bufA[2 + Edim];
    __shared__ __align__(16) float2 bufB[2 + Edim];

    const int n   = blockIdx.x;
    const int tid = threadIdx.x;
    const int L   = tlen[n];
    const int En  = 2 * L + 1;
    const int len = ilen[n];

    // Per-thread static state: extended label + skip flag.
    const int s = tid;
    const bool active = (s < En);
    int  lab = 0;
    bool sk  = false;
    if (active && (s & 1)) {
        lab = y[n * Sdim + (s >> 1)];
        if (s >= 3) sk = (lab != y[n * Sdim + ((s - 2) >> 1)]);
    }

    // Init both alpha buffers (incl. pads) to the zero state {0, BIGE}.
    const float2 ZERO2 = make_float2(0.f, __int_as_float(BIGE));
    for (int i = tid; i < 2 + Edim; i += THREADS) { bufA[i] = ZERO2; bufB[i] = ZERO2; }

    const float*  xbase   = x + (size_t)n * Cdim;      // + t*Nb*Cdim for row t
    const size_t  rstride = (size_t)Nb * Cdim;         // floats per timestep
    const uint32_t sxrow  = (uint32_t)__cvta_generic_to_shared(&xrow[0][0]);

    // Prefetch role: warp 16 (tids 512..543). 32 threads x 2 x 16B = 1024B row.
    const bool pf   = (tid >= 512);
    const int  lane = tid - 512;

    // ---- Prologue: prefetch rows 0..DEPTH-2, publish row 0 ----
    if (pf) {
        #pragma unroll
        for (int t0 = 0; t0 < DEPTH - 1; ++t0) {
            const float* g = xbase + (size_t)t0 * rstride + lane * 8;
            uint32_t     a = sxrow + (uint32_t)(t0 * Cdim + lane * 8) * 4;
            cp_async16(a,      g);
            cp_async16(a + 16, g + 4);
            cp_commit();
        }
        cp_wait<DEPTH - 2>();   // row 0 complete
    }
    __syncthreads();

    // alpha_0 init: states 0,1 from log2-value a0 -> (mant, exp)
    if (tid <= 1 && tid < En) {
        const float a0 = xrow[0][(tid == 0) ? 0 : lab] * LOG2E;
        const float fe = floorf(a0);
        bufA[2 + tid] = make_float2(exp2f(a0 - fe), __int_as_float((int)fe));
    }

    if (pf) {
        const float* g = xbase + (size_t)(DEPTH - 1) * rstride + lane * 8;
        uint32_t     a = sxrow + (uint32_t)((DEPTH - 1) * Cdim + lane * 8) * 4;
        cp_async16(a,      g);
        cp_async16(a + 16, g + 4);
        cp_commit();
        cp_wait<DEPTH - 2>();   // row 1 complete
    }
    __syncthreads();

    float2* Acur  = bufA;
    float2* Bnext = bufB;

    // Own previous alpha in registers.
    float a_m = 0.f;
    int   a_e = BIGE;
    if (active) { float2 o = Acur[2 + s]; a_m = o.x; a_e = __float_as_int(o.y); }

    int slot_rd = 1;   // slot holding row t (t starts at 1)
    int slot_wr = 0;   // slot to overwrite: (t-1) % DEPTH

    for (int t = 1; t < len; ++t) {
        // -- alpha update (row t published by previous barrier) --
        if (active) {
            // p = 2^(x*log2e): only MUFU op, independent of the alpha chain.
            const float p  = exp2f(xrow[slot_rd][lab] * LOG2E);

            const float2 n2 = Acur[s];       // alpha[s-2]
            const float2 n1 = Acur[1 + s];   // alpha[s-1]
            const int e2 = __float_as_int(n1.y);
            const int e3 = sk ? __float_as_int(n2.y) : BIGE;
            const float m3 = sk ? n2.x : 0.f;

            const int em = max(a_e, max(e2, e3));
            float sum = a_m * pow2i(a_e - em);
            sum = fmaf(n1.x, pow2i(e2 - em), sum);
            sum = fmaf(m3,   pow2i(e3 - em), sum);

            const float v = sum * p;   // sum >= 1 when nonzero; p normal -> v normal or 0

            // renormalize v -> (mant in [1,2), exponent)
            const int vb = __float_as_int(v);
            int   en   = em + ((vb >> 23) - 127);
            float mant = __int_as_float((vb & 0x007fffff) | 0x3f800000);
            if (v == 0.f) { mant = 0.f; en = BIGE; }   // still-unreached states

            Bnext[2 + s] = make_float2(mant, __int_as_float(en));
            a_m = mant; a_e = en;
        }

        // -- prefetch row t+DEPTH-1 into the slot consumed last iteration --
        if (pf) {
            int tr = t + DEPTH - 1;
            if (tr > Tdim - 1) tr = Tdim - 1;   // clamped rows never consumed
            const float* g = xbase + (size_t)tr * rstride + lane * 8;
            uint32_t     a = sxrow + (uint32_t)(slot_wr * Cdim + lane * 8) * 4;
            cp_async16(a,      g);
            cp_async16(a + 16, g + 4);
            cp_commit();
            cp_wait<DEPTH - 2>();               // row t+1 complete
        }

        __syncthreads();   // publishes Bnext and row t+1

        // advance ring slots without modulo
        slot_rd = (slot_rd + 1 == DEPTH) ? 0 : slot_rd + 1;
        slot_wr = (slot_wr + 1 == DEPTH) ? 0 : slot_wr + 1;

        // swap alpha buffers
        float2* tmp = Acur; Acur = Bnext; Bnext = tmp;
    }

    if (tid == 0) {
        // log2(alpha) = e + log2(mant); logaddexp of the two final states.
        const float2 A1 = Acur[2 + (2 * L - 1)];
        const float2 A2 = Acur[2 + 2 * L];
        const float l1 = (A1.x == 0.f) ? NEGL
                         : (float)__float_as_int(A1.y) + log2f(A1.x);
        const float l2 = (A2.x == 0.f) ? NEGL
                         : (float)__float_as_int(A2.y) + log2f(A2.x);
        const float m  = fmaxf(l1, l2);
        const float ll2 = m + log2f(exp2f(l1 - m) + exp2f(l2 - m));
        g_block_loss[n] = -(ll2 * LN2) / (float)L;
    }
}

__global__ void ctc_reduce_kernel(float* __restrict__ out)
{
    const int tid = threadIdx.x;   // 64 threads
    float v = g_block_loss[tid];
    #pragma unroll
    for (int off = 16; off > 0; off >>= 1)
        v += __shfl_xor_sync(0xffffffffu, v, off);
    __shared__ float w[2];
    if ((tid & 31) == 0) w[tid >> 5] = v;
    __syncthreads();
    if (tid == 0) out[0] = (w[0] + w[1]) * (1.0f / (float)Nb);
}

extern "C" void kernel_launch(void* const* d_in, const int* in_sizes, int n_in,
                              void* d_out, int out_size)
{
    (void)in_sizes; (void)n_in; (void)out_size;
    const float* x  = (const float*)d_in[0];
    const int*   y  = (const int*)d_in[1];
    const int*   il = (const int*)d_in[2];
    const int*   tl = (const int*)d_in[3];

    ctc_alpha_kernel<<<Nb, THREADS>>>(x, y, il, tl);
    ctc_reduce_kernel<<<1, 64>>>((float*)d_out);
}